// round 15
// baseline (speedup 1.0000x reference)
#include <cuda_runtime.h>
#include <cstdint>

#define T_STEPS 512
#define N_SIM   32
#define N_PROD  116
#define N_TILES (T_STEPS * 32)

__device__ __align__(8) float g_w3t[401 * 120];       // conv3 weights [k][o]; row 400 = zeros
__device__ float g_drive1[(size_t)N_TILES * 4704];    // conv1 drive [t][b][4704]
__device__ int   g_ready[N_TILES];

// ---------------- threefry2x32 (JAX), 20 rounds ----------------
__device__ __forceinline__ void threefry(unsigned k0, unsigned k1,
                                         unsigned x0, unsigned x1,
                                         unsigned &o0, unsigned &o1)
{
    unsigned k2 = k0 ^ k1 ^ 0x1BD11BDAu;
    x0 += k0; x1 += k1;
#define TF_R(r) { x0 += x1; x1 = __funnelshift_l(x1, x1, (r)); x1 ^= x0; }
    TF_R(13) TF_R(15) TF_R(26) TF_R(6)
    x0 += k1; x1 += k2 + 1u;
    TF_R(17) TF_R(29) TF_R(16) TF_R(24)
    x0 += k2; x1 += k0 + 2u;
    TF_R(13) TF_R(15) TF_R(26) TF_R(6)
    x0 += k0; x1 += k1 + 3u;
    TF_R(17) TF_R(29) TF_R(16) TF_R(24)
    x0 += k1; x1 += k2 + 4u;
    TF_R(13) TF_R(15) TF_R(26) TF_R(6)
    x0 += k2; x1 += k0 + 5u;
#undef TF_R
    o0 = x0; o1 = x1;
}

__global__ void __launch_bounds__(1024) reset_kernel()
{
    int i = blockIdx.x * 1024 + threadIdx.x;
    if (i < N_TILES) g_ready[i] = 0;
}

__global__ void __launch_bounds__(256) w3t_kernel(const float* __restrict__ w3)
{
    int i = blockIdx.x * 256 + threadIdx.x;   // 48120 (row 400 forced to 0)
    if (i < 48000) {
        int k = i / 120, o = i % 120;
        g_w3t[i] = w3[o * 400 + k];
    } else if (i < 48120) {
        g_w3t[i] = 0.0f;
    }
}

typedef unsigned long long u64;
__device__ __forceinline__ void add2(u64 &acc, u64 p)
{
    asm("add.rn.f32x2 %0, %1, %2;" : "=l"(acc) : "l"(p), "l"(acc));
}
__device__ __forceinline__ float2 u2f(u64 v)
{
    float2 r;
    asm("mov.b64 {%0, %1}, %2;" : "=f"(r.x), "=f"(r.y) : "l"(v));
    return r;
}

// ---------------- shared memory map (float offsets) ----------------
#define SM_DRV    0        // 9408 = 2 x 4704 drive double buffer
#define SM_SKB    9408     // 1176
#define SM_M12A   10584    // 9408
#define SM_M12C   19992    // 3200
#define SM_PARTB  23192    // 9600
#define SM_PARTC  32792    // 840 = 7 x 120
#define SM_SKE    33632    // 120
#define SM_M12F   33752    // 168
#define SM_SKF    33920    // 84
#define SM_ACC    34024    // 10
#define SM_WCNT   34034    // 13 ints
#define SM_LIST   34048    // 416 ints
#define SM_W2     34464    // 2400
#define SM_FW1    36864    // 10080
#define SM_FW2    46944    // 840
#define SM_TOTAL  47784
#define SMEM_BYTES (SM_TOTAL * 4)
#define SM_ZBEG   SM_SKB
#define SM_ZEND   SM_W2
// producer view
#define PM_XF     0
#define PM_W1     1024

__global__ void __launch_bounds__(1024, 1)
fused_kernel(const float* __restrict__ image, const float* __restrict__ w1,
             const float* __restrict__ w2, const float* __restrict__ fw1,
             const float* __restrict__ fw2, float* __restrict__ out)
{
    extern __shared__ float sm[];
    const int tid  = threadIdx.x;
    const int lane = tid & 31;
    const int wrp  = tid >> 5;

    if (blockIdx.x >= N_SIM) {
        // ================= PRODUCER: RNG + conv1 =================
        const int p = blockIdx.x - N_SIM;
        if (tid < 150) sm[PM_W1 + tid] = w1[tid];
        __syncthreads();
        const int c1_c  = tid / 112;
        const int c1_r  = tid % 112;
        const int c1_oy = c1_r >> 2;
        const int c1_x0 = (c1_r & 3) * 7;

        for (int idx = p; idx < N_TILES; idx += N_PROD) {
            int t = idx >> 5, b = idx & 31;
            unsigned k0, k1;
            threefry(0u, 1u, 0u, (unsigned)t, k0, k1);
            unsigned o0, o1;
            threefry(k0, k1, 0u, (unsigned)(b * 1024 + tid), o0, o1);
            unsigned bits = o0 ^ o1;
            float u = __uint_as_float(0x3f800000u | (bits >> 9)) - 1.0f;
            float r = __ldg(image + b * 1024 + tid) * 0.1953125f;
            sm[PM_XF + tid] = (r > u) ? 1.f : 0.f;
            __syncthreads();

            if (tid < 672) {
                const float* wr = sm + PM_W1 + c1_c * 25;
                float acc[7];
#pragma unroll
                for (int o = 0; o < 7; o++) acc[o] = 0.f;
#pragma unroll
                for (int ky = 0; ky < 5; ky++) {
                    const float* row = sm + PM_XF + (c1_oy + ky) * 32 + c1_x0;
                    float in[11];
#pragma unroll
                    for (int q = 0; q < 11; q++) in[q] = row[q];
#pragma unroll
                    for (int kx = 0; kx < 5; kx++) {
                        float wv = wr[ky * 5 + kx];
#pragma unroll
                        for (int o = 0; o < 7; o++)
                            acc[o] = fmaf(wv, in[kx + o], acc[o]);
                    }
                }
                float* outp = g_drive1 + (size_t)idx * 4704
                            + c1_c * 784 + c1_oy * 28 + c1_x0;
#pragma unroll
                for (int o = 0; o < 7; o++) outp[o] = acc[o];
            }
            __syncthreads();
            if (tid == 0) {
                __threadfence();
                ((volatile int*)g_ready)[idx] = 1;
            }
        }
        return;
    }

    // ================= SIM CTA (one per batch element) =================
    int* const wcnt  = (int*)(sm + SM_WCNT);
    int* const listi = (int*)(sm + SM_LIST);
    const int b = blockIdx.x;

    for (int i = tid; i < 2400;  i += 1024) sm[SM_W2  + i] = w2[i];
    for (int i = tid; i < 10080; i += 1024) sm[SM_FW1 + i] = fw1[i];
    for (int i = tid; i < 840;   i += 1024) sm[SM_FW2 + i] = fw2[i];
    for (int i = tid; i < (SM_ZEND - SM_ZBEG); i += 1024) sm[SM_ZBEG + i] = 0.0f;
    if (tid == 0) {
        while (((volatile int*)g_ready)[b] == 0) __nanosleep(64);
    }
    __syncthreads();
    __threadfence();
    {
        const float4* src = (const float4*)(g_drive1 + (size_t)b * 4704);
        float4* dst = (float4*)(sm + SM_DRV);
        for (int i = tid; i < 1176; i += 1024) dst[i] = src[i];
    }
    __syncthreads();

    // ---- static mappings ----
    const int c2_g   = tid >> 4;               // B1: tid<480
    const int c2_oc  = tid & 15;
    const int c2_ic  = c2_g / 5;
    const int c2_oy2 = c2_g % 5;
    const int c_sp = tid >> 6;                 // C1: tid<512, 8 splits x 64
    const int c_o2 = tid & 63;

    // register-resident LIF state
    float pmA1[6], pmA2[6];                    // layer2 pooled (A warps 16-23, 3 items x 2)
#pragma unroll
    for (int i = 0; i < 6; i++) { pmA1[i] = 0.f; pmA2[i] = 0.f; }
    float qm1 = 0.f, qm2 = 0.f;                // layer4 pooled (B2)
    float em1a = 0.f, em2a = 0.f, em1b = 0.f, em2b = 0.f;  // layer5 (C2)
    float gm1 = 0.f, gm2 = 0.f;                // layer7 (E warps 13-15)

    // ---- inline phase bodies ----
    auto do_A = [&](int slot) {                // tids 512..767; lif1+pool+lif2
        const int base = tid - 512;
#pragma unroll
        for (int j = 0; j < 3; j++) {
            int item = base + 256 * j;
            if (item < 588) {
                int c = item / 98, r = item % 98;
                int by = r / 7, pq = r % 7;
                const float* dp = sm + SM_DRV + slot * 4704
                                + c * 784 + (2 * by) * 28 + 4 * pq;
                float4 v0 = *(const float4*)dp;
                float4 v1 = *(const float4*)(dp + 28);
                float acc[8] = {v0.x, v0.y, v0.z, v0.w, v1.x, v1.y, v1.z, v1.w};
                int ob = c * 784 + (2 * by) * 28 + 4 * pq;
                float ps[2] = {0.f, 0.f};
#pragma unroll
                for (int q = 0; q < 8; q++) {
                    int oy = q >> 2, jx = q & 3;
                    int o = ob + oy * 28 + jx;
                    float2 m = *(float2*)(sm + SM_M12A + 2 * o);
                    float oms = (m.y > 0.3f) ? 0.f : 1.f;
                    float n1 = m.x * 0.25f * oms + acc[q];
                    float n2 = m.y * 0.25f * oms + 0.5f * n1;
                    *(float2*)(sm + SM_M12A + 2 * o) = make_float2(n1, n2);
                    ps[jx >> 1] += (n2 > 0.3f) ? 1.f : 0.f;
                }
#pragma unroll
                for (int h = 0; h < 2; h++) {
                    float d   = 0.25f * ps[h];
                    float oms = (pmA2[2 * j + h] > 0.3f) ? 0.f : 1.f;
                    float n1  = pmA1[2 * j + h] * 0.25f * oms + d;
                    float n2  = pmA2[2 * j + h] * 0.25f * oms + 0.5f * n1;
                    pmA1[2 * j + h] = n1; pmA2[2 * j + h] = n2;
                    sm[SM_SKB + c * 196 + by * 14 + 2 * pq + h] = (n2 > 0.3f) ? 1.f : 0.f;
                }
            }
        }
    };

    auto do_D = [&]() {                        // tids 544..895; fc1 + lif6
        const int local = tid - 544;           // 0..351
        int g = local >> 2, j = local & 3;
        int gg = (g < 84) ? g : 83;
        const float* wp = sm + SM_FW1 + gg * 120;
        float s = 0.f;
#pragma unroll 6
        for (int k = j; k < 120; k += 4) s = fmaf(wp[k], sm[SM_SKE + k], s);
        s += __shfl_xor_sync(0xffffffffu, s, 2);
        s += __shfl_xor_sync(0xffffffffu, s, 1);
        if (j == 0 && g < 84) {
            float2 m = *(float2*)(sm + SM_M12F + 2 * g);
            float oms = (m.y > 0.3f) ? 0.f : 1.f;
            float n1 = m.x * 0.25f * oms + s;
            float n2 = m.y * 0.25f * oms + 0.5f * n1;
            *(float2*)(sm + SM_M12F + 2 * g) = make_float2(n1, n2);
            sm[SM_SKF + g] = (n2 > 0.3f) ? 1.f : 0.f;
        }
    };

    auto do_E = [&]() {                        // tids 416..511; fc2 + lif7 + acc
        const int local = tid - 416;           // 0..95
        int o = local >> 3, j = local & 7;
        int oo = (o < 10) ? o : 9;
        const float* wp = sm + SM_FW2 + oo * 84;
        float s = 0.f;
#pragma unroll 4
        for (int k = j; k < 84; k += 8) s = fmaf(wp[k], sm[SM_SKF + k], s);
        s += __shfl_xor_sync(0xffffffffu, s, 4);
        s += __shfl_xor_sync(0xffffffffu, s, 2);
        s += __shfl_xor_sync(0xffffffffu, s, 1);
        if (j == 0 && o < 10) {
            float oms = (gm2 > 0.3f) ? 0.f : 1.f;
            float n1 = gm1 * 0.25f * oms + s;
            float n2 = gm2 * 0.25f * oms + 0.5f * n1;
            gm1 = n1; gm2 = n2;
            sm[SM_ACC + o] += (n2 > 0.3f) ? 1.f : 0.f;
        }
    };

    // ---- prologue: A(0) ----
    if (tid >= 512 && tid < 768) do_A(0);
    __syncthreads();

#pragma unroll 1
    for (int t = 0; t < T_STEPS; t++) {
        // ======== P1: B1(t) || pf(t+1) || D(t-1) ========
        if (tid < 480) {
            const float* wr = sm + SM_W2 + (c2_oc * 6 + c2_ic) * 25;
            const float* ib = sm + SM_SKB + c2_ic * 196;
            float acc[20];
#pragma unroll
            for (int q = 0; q < 20; q++) acc[q] = 0.f;
#pragma unroll
            for (int r = 0; r < 6; r++) {
                const float2* rp = (const float2*)(ib + (2 * c2_oy2 + r) * 14);
                float in[14];
#pragma unroll
                for (int k = 0; k < 7; k++) {
                    float2 v = rp[k];
                    in[2 * k] = v.x; in[2 * k + 1] = v.y;
                }
                if (r < 5) {
#pragma unroll
                    for (int kx = 0; kx < 5; kx++) {
                        float wv = wr[r * 5 + kx];
#pragma unroll
                        for (int ox = 0; ox < 10; ox++)
                            acc[ox] = fmaf(wv, in[kx + ox], acc[ox]);
                    }
                }
                if (r >= 1) {
#pragma unroll
                    for (int kx = 0; kx < 5; kx++) {
                        float wv = wr[(r - 1) * 5 + kx];
#pragma unroll
                        for (int ox = 0; ox < 10; ox++)
                            acc[10 + ox] = fmaf(wv, in[kx + ox], acc[10 + ox]);
                    }
                }
            }
            float2* pp = (float2*)(sm + SM_PARTB + c2_ic * 1600 + c2_oc * 100 + (2 * c2_oy2) * 10);
#pragma unroll
            for (int q = 0; q < 10; q++)
                pp[q] = make_float2(acc[2 * q], acc[2 * q + 1]);
        } else if (tid < 544) {
            if (t + 1 < T_STEPS) {
                int idx = (t + 1) * 32 + b;
                if (lane == 0) {
                    while (((volatile int*)g_ready)[idx] == 0) __nanosleep(64);
                }
                __syncwarp();
                __threadfence();
                const float4* src = (const float4*)(g_drive1 + (size_t)idx * 4704);
                float4* dst = (float4*)(sm + SM_DRV + ((t + 1) & 1) * 4704);
                for (int i = tid - 480; i < 1176; i += 64) dst[i] = src[i];
            }
        } else if (tid < 896) {
            if (t >= 1) do_D();                // D(t-1) -> SKF
        }
        __syncthreads();

        // ======== P2: B2(t) || E(t-1) || A(t+1) ========
        if (tid < 416) {
            bool spiked = false;
            int myk = 0;
            if (tid < 400) {
                int oc = tid / 25, rem = tid % 25, py = rem / 5, px = rem % 5;
                float s00 = 0.f, s01 = 0.f, s10 = 0.f, s11 = 0.f;
#pragma unroll
                for (int ic = 0; ic < 6; ic++) {
                    const float* pb = sm + SM_PARTB + ic * 1600 + oc * 100;
                    float2 va = *(const float2*)(pb + (2 * py) * 10 + 2 * px);
                    float2 vb = *(const float2*)(pb + (2 * py + 1) * 10 + 2 * px);
                    s00 += va.x; s01 += va.y; s10 += vb.x; s11 += vb.y;
                }
                float dr0[4] = {s00, s01, s10, s11};
                float psum = 0.f;
                int ob = oc * 100 + (2 * py) * 10 + 2 * px;
#pragma unroll
                for (int q = 0; q < 4; q++) {
                    int o = ob + (q >> 1) * 10 + (q & 1);
                    float2 m = *(float2*)(sm + SM_M12C + 2 * o);
                    float oms = (m.y > 0.3f) ? 0.f : 1.f;
                    float n1 = m.x * 0.25f * oms + dr0[q];
                    float n2 = m.y * 0.25f * oms + 0.5f * n1;
                    *(float2*)(sm + SM_M12C + 2 * o) = make_float2(n1, n2);
                    psum += (n2 > 0.3f) ? 1.f : 0.f;
                }
                float d   = 0.25f * psum;
                float oms = (qm2 > 0.3f) ? 0.f : 1.f;
                float n1  = qm1 * 0.25f * oms + d;
                float n2  = qm2 * 0.25f * oms + 0.5f * n1;
                qm1 = n1; qm2 = n2;
                if (n2 > 0.3f) { spiked = true; myk = tid; }
            }
            unsigned bm = __ballot_sync(0xffffffffu, spiked);
            int cnt = __popc(bm);
            if (spiked) listi[wrp * 32 + __popc(bm & ((1u << lane) - 1u))] = myk;
            if (lane == cnt) listi[wrp * 32 + lane] = 400;   // sentinel
            if (lane == 0) wcnt[wrp] = cnt;
        } else if (tid < 512) {
            if (t >= 1) do_E();                // E(t-1)
        } else if (tid < 768) {
            if (t + 1 < T_STEPS) do_A((t + 1) & 1);
        }
        __syncthreads();

        // ======== P3: C1(t) sparse conv3 gather ========
        u64 cacc = 0ull;
        if (tid < 512 && c_o2 < 60) {
            const u64* w3p = (const u64*)g_w3t;
            for (int w = c_sp; w < 13; w += 8) {
                int n = wcnt[w];
                const int* seg = listi + w * 32;
                for (int j = 0; j < n; j += 2) {
                    int k0 = seg[j];
                    int k1 = seg[j + 1];
                    u64 v0 = __ldg(w3p + k0 * 60 + c_o2);
                    u64 v1 = __ldg(w3p + k1 * 60 + c_o2);
                    add2(cacc, v0);
                    add2(cacc, v1);
                }
            }
            if (c_sp) *(u64*)(sm + SM_PARTC + (c_sp - 1) * 120 + 2 * c_o2) = cacc;
        }
        __syncthreads();

        // ======== P4: C2(t) combine + lif5 -> SKE ========
        if (tid < 60) {
#pragma unroll
            for (int s7 = 0; s7 < 7; s7++)
                add2(cacc, *(const u64*)(sm + SM_PARTC + s7 * 120 + 2 * tid));
            float2 v = u2f(cacc);
            float oms = (em2a > 0.3f) ? 0.f : 1.f;
            float n1  = em1a * 0.25f * oms + v.x;
            float n2  = em2a * 0.25f * oms + 0.5f * n1;
            em1a = n1; em2a = n2;
            sm[SM_SKE + 2 * tid] = (n2 > 0.3f) ? 1.f : 0.f;
            float omsb = (em2b > 0.3f) ? 0.f : 1.f;
            float n1b  = em1b * 0.25f * omsb + v.y;
            float n2b  = em2b * 0.25f * omsb + 0.5f * n1b;
            em1b = n1b; em2b = n2b;
            sm[SM_SKE + 2 * tid + 1] = (n2b > 0.3f) ? 1.f : 0.f;
        }
        __syncthreads();
    }

    // ---- epilogue: D(511), E(511) ----
    if (tid >= 544 && tid < 896) do_D();
    __syncthreads();
    if (tid >= 416 && tid < 512) do_E();
    __syncthreads();

    if (tid < 10)
        out[b * 10 + tid] = sm[SM_ACC + tid] * (1.0f / 512.0f);
}

extern "C" void kernel_launch(void* const* d_in, const int* in_sizes, int n_in,
                              void* d_out, int out_size)
{
    const float* image = (const float*)d_in[0];
    const float* w1    = (const float*)d_in[1];
    const float* w2    = (const float*)d_in[2];
    const float* w3    = (const float*)d_in[3];
    const float* fw1   = (const float*)d_in[4];
    const float* fw2   = (const float*)d_in[5];
    float* out = (float*)d_out;

    reset_kernel<<<(N_TILES + 1023) / 1024, 1024>>>();
    w3t_kernel<<<(48120 + 255) / 256, 256>>>(w3);
    cudaFuncSetAttribute(fused_kernel, cudaFuncAttributeMaxDynamicSharedMemorySize, SMEM_BYTES);
    fused_kernel<<<N_SIM + N_PROD, 1024, SMEM_BYTES>>>(image, w1, w2, fw1, fw2, out);
}

// round 16
// speedup vs baseline: 1.1177x; 1.1177x over previous
#include <cuda_runtime.h>
#include <cstdint>

#define T_STEPS 512
#define N_SIM   32
#define N_PROD  116
#define N_TILES (T_STEPS * 32)

__device__ __align__(8) float g_w3t[401 * 120];       // conv3 weights [k][o]; row 400 = zeros
__device__ float g_drive1[(size_t)N_TILES * 4704];    // conv1 drive [t][b][4704]
__device__ int   g_ready[N_TILES];

// ---------------- threefry2x32 (JAX), 20 rounds ----------------
__device__ __forceinline__ void threefry(unsigned k0, unsigned k1,
                                         unsigned x0, unsigned x1,
                                         unsigned &o0, unsigned &o1)
{
    unsigned k2 = k0 ^ k1 ^ 0x1BD11BDAu;
    x0 += k0; x1 += k1;
#define TF_R(r) { x0 += x1; x1 = __funnelshift_l(x1, x1, (r)); x1 ^= x0; }
    TF_R(13) TF_R(15) TF_R(26) TF_R(6)
    x0 += k1; x1 += k2 + 1u;
    TF_R(17) TF_R(29) TF_R(16) TF_R(24)
    x0 += k2; x1 += k0 + 2u;
    TF_R(13) TF_R(15) TF_R(26) TF_R(6)
    x0 += k0; x1 += k1 + 3u;
    TF_R(17) TF_R(29) TF_R(16) TF_R(24)
    x0 += k1; x1 += k2 + 4u;
    TF_R(13) TF_R(15) TF_R(26) TF_R(6)
    x0 += k2; x1 += k0 + 5u;
#undef TF_R
    o0 = x0; o1 = x1;
}

__global__ void __launch_bounds__(1024) reset_kernel()
{
    int i = blockIdx.x * 1024 + threadIdx.x;
    if (i < N_TILES) g_ready[i] = 0;
}

__global__ void __launch_bounds__(256) w3t_kernel(const float* __restrict__ w3)
{
    int i = blockIdx.x * 256 + threadIdx.x;   // 48120 (row 400 forced to 0)
    if (i < 48000) {
        int k = i / 120, o = i % 120;
        g_w3t[i] = w3[o * 400 + k];
    } else if (i < 48120) {
        g_w3t[i] = 0.0f;
    }
}

typedef unsigned long long u64;
__device__ __forceinline__ void add2(u64 &acc, u64 p)
{
    asm("add.rn.f32x2 %0, %1, %2;" : "=l"(acc) : "l"(p), "l"(acc));
}
__device__ __forceinline__ float2 u2f(u64 v)
{
    float2 r;
    asm("mov.b64 {%0, %1}, %2;" : "=f"(r.x), "=f"(r.y) : "l"(v));
    return r;
}

// ---------------- shared memory map (float offsets) ----------------
#define SM_DRV    0        // 9408 = 2 x 4704 drive double buffer
#define SM_SKB    9408     // 1176
#define SM_M12A   10584    // 9408
#define SM_M12C   19992    // 3200
#define SM_PARTB  23192    // 9600
#define SM_SKE    32792    // 120
#define SM_M12F   32912    // 168
#define SM_SKF    33080    // 84
#define SM_M12G   33164    // 20
#define SM_ACC    33184    // 10
#define SM_WCNT   33194    // 13 ints
#define SM_LIST   33208    // 416 ints
#define SM_W2     33624    // 2400
#define SM_FW1    36024    // 10080
#define SM_FW2    46104    // 840
#define SM_TOTAL  46944
#define SMEM_BYTES (SM_TOTAL * 4)
#define SM_ZBEG   SM_SKB
#define SM_ZEND   SM_W2
// producer view of the same smem
#define PM_XF     0
#define PM_W1     1024

__global__ void __launch_bounds__(1024, 1)
fused_kernel(const float* __restrict__ image, const float* __restrict__ w1,
             const float* __restrict__ w2, const float* __restrict__ fw1,
             const float* __restrict__ fw2, float* __restrict__ out)
{
    extern __shared__ float sm[];
    const int tid  = threadIdx.x;
    const int lane = tid & 31;
    const int wrp  = tid >> 5;

    if (blockIdx.x >= N_SIM) {
        // ================= PRODUCER: RNG + conv1 for tiles (t,b) =================
        const int p = blockIdx.x - N_SIM;
        if (tid < 150) sm[PM_W1 + tid] = w1[tid];
        __syncthreads();
        const int c1_c  = tid / 112;           // conv1: tid<672
        const int c1_r  = tid % 112;
        const int c1_oy = c1_r >> 2;
        const int c1_x0 = (c1_r & 3) * 7;

        for (int idx = p; idx < N_TILES; idx += N_PROD) {
            int t = idx >> 5, b = idx & 31;
            unsigned k0, k1;
            threefry(0u, 1u, 0u, (unsigned)t, k0, k1);
            unsigned o0, o1;
            threefry(k0, k1, 0u, (unsigned)(b * 1024 + tid), o0, o1);
            unsigned bits = o0 ^ o1;
            float u = __uint_as_float(0x3f800000u | (bits >> 9)) - 1.0f;
            float r = __ldg(image + b * 1024 + tid) * 0.1953125f;
            sm[PM_XF + tid] = (r > u) ? 1.f : 0.f;
            __syncthreads();

            if (tid < 672) {
                const float* wr = sm + PM_W1 + c1_c * 25;
                float acc[7];
#pragma unroll
                for (int o = 0; o < 7; o++) acc[o] = 0.f;
#pragma unroll
                for (int ky = 0; ky < 5; ky++) {
                    const float* row = sm + PM_XF + (c1_oy + ky) * 32 + c1_x0;
                    float in[11];
#pragma unroll
                    for (int q = 0; q < 11; q++) in[q] = row[q];
#pragma unroll
                    for (int kx = 0; kx < 5; kx++) {
                        float wv = wr[ky * 5 + kx];
#pragma unroll
                        for (int o = 0; o < 7; o++)
                            acc[o] = fmaf(wv, in[kx + o], acc[o]);
                    }
                }
                float* outp = g_drive1 + (size_t)idx * 4704
                            + c1_c * 784 + c1_oy * 28 + c1_x0;
#pragma unroll
                for (int o = 0; o < 7; o++) outp[o] = acc[o];
            }
            __syncthreads();
            if (tid == 0) {
                __threadfence();
                ((volatile int*)g_ready)[idx] = 1;
            }
        }
        return;
    }

    // ================= SIM CTA (one per batch element) =================
    int* const wcnt  = (int*)(sm + SM_WCNT);
    int* const listi = (int*)(sm + SM_LIST);
    const int b = blockIdx.x;

    for (int i = tid; i < 2400;  i += 1024) sm[SM_W2  + i] = w2[i];
    for (int i = tid; i < 10080; i += 1024) sm[SM_FW1 + i] = fw1[i];
    for (int i = tid; i < 840;   i += 1024) sm[SM_FW2 + i] = fw2[i];
    for (int i = tid; i < (SM_ZEND - SM_ZBEG); i += 1024) sm[SM_ZBEG + i] = 0.0f;
    if (tid == 0) {
        while (((volatile int*)g_ready)[b] == 0) __nanosleep(64);
    }
    __syncthreads();
    __threadfence();
    {
        const float4* src = (const float4*)(g_drive1 + (size_t)b * 4704);
        float4* dst = (float4*)(sm + SM_DRV);
        for (int i = tid; i < 1176; i += 1024) dst[i] = src[i];
    }
    __syncthreads();

    // ---- static mappings ----
    const int a_l  = tid - 320;                // A: tids [320, 908) (c, by, p)
    const int a_c  = a_l / 98;
    const int a_r  = a_l % 98;
    const int a_by = a_r / 7;
    const int a_p  = a_r % 7;
    const int c2_g   = tid >> 4;               // B1: tid<480, g=(ic*5+oy2), lane16=oc
    const int c2_oc  = tid & 15;
    const int c2_ic  = c2_g / 5;
    const int c2_oy2 = c2_g % 5;
    const int c_o2 = tid >> 3;                 // C fused: tid<480, o2<60, 8-lane groups
    const int c_j  = tid & 7;
    const int d_g  = tid >> 3;                 // D: tid<672
    const int d_j  = tid & 7;

    // register-resident LIF state
    float pm1[2] = {0.f, 0.f}, pm2[2] = {0.f, 0.f};       // layer2 pooled (A warps)
    float qm1 = 0.f, qm2 = 0.f;                            // layer4 pooled (B2 warps)
    float em1a = 0.f, em2a = 0.f, em1b = 0.f, em2b = 0.f;  // layer5 (C j==0 threads)

#pragma unroll 1
    for (int t = 0; t < T_STEPS; t++) {
        // ---- A(t) on tids 320..907  ||  E(t-1) on warps 0..9 ----
        if (tid >= 320 && tid < 908) {
            const float* dp = sm + SM_DRV + (t & 1) * 4704
                            + a_c * 784 + (2 * a_by) * 28 + 4 * a_p;
            float4 v0 = *(const float4*)dp;
            float4 v1 = *(const float4*)(dp + 28);
            float acc[8] = {v0.x, v0.y, v0.z, v0.w, v1.x, v1.y, v1.z, v1.w};
            int ob = a_c * 784 + (2 * a_by) * 28 + 4 * a_p;
            float ps[2] = {0.f, 0.f};
#pragma unroll
            for (int q = 0; q < 8; q++) {
                int oy = q >> 2, j = q & 3;
                int o = ob + oy * 28 + j;
                float2 m = *(float2*)(sm + SM_M12A + 2 * o);
                float oms = (m.y > 0.3f) ? 0.f : 1.f;
                float n1 = m.x * 0.25f * oms + acc[q];
                float n2 = m.y * 0.25f * oms + 0.5f * n1;
                *(float2*)(sm + SM_M12A + 2 * o) = make_float2(n1, n2);
                ps[j >> 1] += (n2 > 0.3f) ? 1.f : 0.f;
            }
#pragma unroll
            for (int h = 0; h < 2; h++) {
                float d   = 0.25f * ps[h];
                float oms = (pm2[h] > 0.3f) ? 0.f : 1.f;
                float n1  = pm1[h] * 0.25f * oms + d;
                float n2  = pm2[h] * 0.25f * oms + 0.5f * n1;
                pm1[h] = n1; pm2[h] = n2;
                sm[SM_SKB + a_c * 196 + a_by * 14 + 2 * a_p + h] = (n2 > 0.3f) ? 1.f : 0.f;
            }
        } else if (wrp < 10 && t > 0) {
            // E(t-1): fc2 + lif7 + acc
            const float* wp = sm + SM_FW2 + wrp * 84;
            float s = 0.f;
            for (int k = lane; k < 84; k += 32) s = fmaf(wp[k], sm[SM_SKF + k], s);
#pragma unroll
            for (int d2 = 16; d2 > 0; d2 >>= 1) s += __shfl_xor_sync(0xffffffffu, s, d2);
            if (lane == 0) {
                float2 m = *(float2*)(sm + SM_M12G + 2 * wrp);
                float oms = (m.y > 0.3f) ? 0.f : 1.f;
                float n1 = m.x * 0.25f * oms + s;
                float n2 = m.y * 0.25f * oms + 0.5f * n1;
                *(float2*)(sm + SM_M12G + 2 * wrp) = make_float2(n1, n2);
                sm[SM_ACC + wrp] += (n2 > 0.3f) ? 1.f : 0.f;
            }
        }
        __syncthreads();

        // ---- B1: conv2 partials (lane16=oc broadcast) | drive prefetch ----
        if (tid < 480) {
            const float* wr = sm + SM_W2 + (c2_oc * 6 + c2_ic) * 25;
            const float* ib = sm + SM_SKB + c2_ic * 196;
            float acc[20];
#pragma unroll
            for (int q = 0; q < 20; q++) acc[q] = 0.f;
#pragma unroll
            for (int r = 0; r < 6; r++) {
                const float2* rp = (const float2*)(ib + (2 * c2_oy2 + r) * 14);
                float in[14];
#pragma unroll
                for (int k = 0; k < 7; k++) {
                    float2 v = rp[k];
                    in[2 * k] = v.x; in[2 * k + 1] = v.y;
                }
                if (r < 5) {
#pragma unroll
                    for (int kx = 0; kx < 5; kx++) {
                        float wv = wr[r * 5 + kx];
#pragma unroll
                        for (int ox = 0; ox < 10; ox++)
                            acc[ox] = fmaf(wv, in[kx + ox], acc[ox]);
                    }
                }
                if (r >= 1) {
#pragma unroll
                    for (int kx = 0; kx < 5; kx++) {
                        float wv = wr[(r - 1) * 5 + kx];
#pragma unroll
                        for (int ox = 0; ox < 10; ox++)
                            acc[10 + ox] = fmaf(wv, in[kx + ox], acc[10 + ox]);
                    }
                }
            }
            float2* pp = (float2*)(sm + SM_PARTB + c2_ic * 1600 + c2_oc * 100 + (2 * c2_oy2) * 10);
#pragma unroll
            for (int q = 0; q < 10; q++)
                pp[q] = make_float2(acc[2 * q], acc[2 * q + 1]);
        } else if (t + 1 < T_STEPS) {
            int idx = (t + 1) * 32 + b;
            if (lane == 0) {
                while (((volatile int*)g_ready)[idx] == 0) __nanosleep(64);
            }
            __syncwarp();
            __threadfence();
            const float4* src = (const float4*)(g_drive1 + (size_t)idx * 4704);
            float4* dst = (float4*)(sm + SM_DRV + ((t + 1) & 1) * 4704);
            for (int i = tid - 480; i < 1176; i += 544) dst[i] = src[i];
        }
        __syncthreads();

        // ---- B2: reduce ic + lif3 + pool + lif4 + padded spike segments ----
        bool spiked = false;
        int myk = 0;
        if (tid < 400) {
            int oc = tid / 25, rem = tid % 25, py = rem / 5, px = rem % 5;
            float s00 = 0.f, s01 = 0.f, s10 = 0.f, s11 = 0.f;
#pragma unroll
            for (int ic = 0; ic < 6; ic++) {
                const float* pb = sm + SM_PARTB + ic * 1600 + oc * 100;
                float2 va = *(const float2*)(pb + (2 * py) * 10 + 2 * px);
                float2 vb = *(const float2*)(pb + (2 * py + 1) * 10 + 2 * px);
                s00 += va.x; s01 += va.y; s10 += vb.x; s11 += vb.y;
            }
            float dr0[4] = {s00, s01, s10, s11};
            float psum = 0.f;
            int ob = oc * 100 + (2 * py) * 10 + 2 * px;
#pragma unroll
            for (int q = 0; q < 4; q++) {
                int o = ob + (q >> 1) * 10 + (q & 1);
                float2 m = *(float2*)(sm + SM_M12C + 2 * o);
                float oms = (m.y > 0.3f) ? 0.f : 1.f;
                float n1 = m.x * 0.25f * oms + dr0[q];
                float n2 = m.y * 0.25f * oms + 0.5f * n1;
                *(float2*)(sm + SM_M12C + 2 * o) = make_float2(n1, n2);
                psum += (n2 > 0.3f) ? 1.f : 0.f;
            }
            float d   = 0.25f * psum;
            float oms = (qm2 > 0.3f) ? 0.f : 1.f;
            float n1  = qm1 * 0.25f * oms + d;
            float n2  = qm2 * 0.25f * oms + 0.5f * n1;
            qm1 = n1; qm2 = n2;
            if (n2 > 0.3f) { spiked = true; myk = tid; }
        }
        if (wrp < 13) {
            unsigned bm = __ballot_sync(0xffffffffu, spiked);
            int cnt = __popc(bm);
            if (spiked) listi[wrp * 32 + __popc(bm & ((1u << lane) - 1u))] = myk;
            if (lane == cnt) listi[wrp * 32 + lane] = 400;   // sentinel pad (zero row)
            if (lane == 0) wcnt[wrp] = cnt;
        }
        __syncthreads();

        // ---- C fused: gather + 8-lane shfl reduce + lif5 -> SKE ----
        if (tid < 480) {
            const u64* w3p = (const u64*)g_w3t;
            u64 cacc = 0ull;
            for (int w = c_j; w < 13; w += 8) {
                int n = wcnt[w];
                const int* seg = listi + w * 32;
                for (int j = 0; j < n; j += 2) {
                    int k0 = seg[j];
                    int k1 = seg[j + 1];          // may be sentinel 400 (zero row)
                    u64 v0 = __ldg(w3p + k0 * 60 + c_o2);
                    u64 v1 = __ldg(w3p + k1 * 60 + c_o2);
                    add2(cacc, v0);
                    add2(cacc, v1);
                }
            }
            add2(cacc, __shfl_xor_sync(0xffffffffu, cacc, 4));
            add2(cacc, __shfl_xor_sync(0xffffffffu, cacc, 2));
            add2(cacc, __shfl_xor_sync(0xffffffffu, cacc, 1));
            if (c_j == 0) {
                float2 v = u2f(cacc);
                float oms = (em2a > 0.3f) ? 0.f : 1.f;
                float n1  = em1a * 0.25f * oms + v.x;
                float n2  = em2a * 0.25f * oms + 0.5f * n1;
                em1a = n1; em2a = n2;
                sm[SM_SKE + 2 * c_o2] = (n2 > 0.3f) ? 1.f : 0.f;
                float omsb = (em2b > 0.3f) ? 0.f : 1.f;
                float n1b  = em1b * 0.25f * omsb + v.y;
                float n2b  = em2b * 0.25f * omsb + 0.5f * n1b;
                em1b = n1b; em2b = n2b;
                sm[SM_SKE + 2 * c_o2 + 1] = (n2b > 0.3f) ? 1.f : 0.f;
            }
        }
        __syncthreads();

        // ---- D: fc1 + lif6 -> SKF ----
        if (tid < 672) {
            const float* wp = sm + SM_FW1 + d_g * 120;
            float s = 0.f;
#pragma unroll
            for (int k = d_j; k < 120; k += 8) s = fmaf(wp[k], sm[SM_SKE + k], s);
            s += __shfl_xor_sync(0xffffffffu, s, 4);
            s += __shfl_xor_sync(0xffffffffu, s, 2);
            s += __shfl_xor_sync(0xffffffffu, s, 1);
            if (d_j == 0) {
                float2 m = *(float2*)(sm + SM_M12F + 2 * d_g);
                float oms = (m.y > 0.3f) ? 0.f : 1.f;
                float n1 = m.x * 0.25f * oms + s;
                float n2 = m.y * 0.25f * oms + 0.5f * n1;
                *(float2*)(sm + SM_M12F + 2 * d_g) = make_float2(n1, n2);
                sm[SM_SKF + d_g] = (n2 > 0.3f) ? 1.f : 0.f;
            }
        }
        __syncthreads();
    }

    // ---- drain: E(T_STEPS-1) ----
    if (wrp < 10) {
        const float* wp = sm + SM_FW2 + wrp * 84;
        float s = 0.f;
        for (int k = lane; k < 84; k += 32) s = fmaf(wp[k], sm[SM_SKF + k], s);
#pragma unroll
        for (int d2 = 16; d2 > 0; d2 >>= 1) s += __shfl_xor_sync(0xffffffffu, s, d2);
        if (lane == 0) {
            float2 m = *(float2*)(sm + SM_M12G + 2 * wrp);
            float oms = (m.y > 0.3f) ? 0.f : 1.f;
            float n1 = m.x * 0.25f * oms + s;
            float n2 = m.y * 0.25f * oms + 0.5f * n1;
            sm[SM_ACC + wrp] += (n2 > 0.3f) ? 1.f : 0.f;
        }
    }
    __syncthreads();

    if (tid < 10)
        out[b * 10 + tid] = sm[SM_ACC + tid] * (1.0f / 512.0f);
}

extern "C" void kernel_launch(void* const* d_in, const int* in_sizes, int n_in,
                              void* d_out, int out_size)
{
    const float* image = (const float*)d_in[0];
    const float* w1    = (const float*)d_in[1];
    const float* w2    = (const float*)d_in[2];
    const float* w3    = (const float*)d_in[3];
    const float* fw1   = (const float*)d_in[4];
    const float* fw2   = (const float*)d_in[5];
    float* out = (float*)d_out;

    reset_kernel<<<(N_TILES + 1023) / 1024, 1024>>>();
    w3t_kernel<<<(48120 + 255) / 256, 256>>>(w3);
    cudaFuncSetAttribute(fused_kernel, cudaFuncAttributeMaxDynamicSharedMemorySize, SMEM_BYTES);
    fused_kernel<<<N_SIM + N_PROD, 1024, SMEM_BYTES>>>(image, w1, w2, fw1, fw2, out);
}

// round 17
// speedup vs baseline: 1.2898x; 1.1540x over previous
#include <cuda_runtime.h>
#include <cstdint>

#define T_STEPS 512
#define N_SIM   64          // 32 pairs (cluster of 2)
#define N_PROD  84
#define N_TILES (T_STEPS * 32)

__device__ __align__(8) float g_w3t[401 * 120];       // conv3 weights [k][o]; row 400 zeros
__device__ float g_drive1[(size_t)N_TILES * 4704];
__device__ int   g_ready[N_TILES];

// ---------------- threefry2x32 (JAX), 20 rounds ----------------
__device__ __forceinline__ void threefry(unsigned k0, unsigned k1,
                                         unsigned x0, unsigned x1,
                                         unsigned &o0, unsigned &o1)
{
    unsigned k2 = k0 ^ k1 ^ 0x1BD11BDAu;
    x0 += k0; x1 += k1;
#define TF_R(r) { x0 += x1; x1 = __funnelshift_l(x1, x1, (r)); x1 ^= x0; }
    TF_R(13) TF_R(15) TF_R(26) TF_R(6)
    x0 += k1; x1 += k2 + 1u;
    TF_R(17) TF_R(29) TF_R(16) TF_R(24)
    x0 += k2; x1 += k0 + 2u;
    TF_R(13) TF_R(15) TF_R(26) TF_R(6)
    x0 += k0; x1 += k1 + 3u;
    TF_R(17) TF_R(29) TF_R(16) TF_R(24)
    x0 += k1; x1 += k2 + 4u;
    TF_R(13) TF_R(15) TF_R(26) TF_R(6)
    x0 += k2; x1 += k0 + 5u;
#undef TF_R
    o0 = x0; o1 = x1;
}

__global__ void __launch_bounds__(1024) reset_kernel()
{
    int i = blockIdx.x * 1024 + threadIdx.x;
    if (i < N_TILES) g_ready[i] = 0;
}

__global__ void __launch_bounds__(256) w3t_kernel(const float* __restrict__ w3)
{
    int i = blockIdx.x * 256 + threadIdx.x;
    if (i < 48000) {
        int k = i / 120, o = i % 120;
        g_w3t[i] = w3[o * 400 + k];
    } else if (i < 48120) {
        g_w3t[i] = 0.0f;
    }
}

typedef unsigned long long u64;
__device__ __forceinline__ void add2(u64 &acc, u64 p)
{
    asm("add.rn.f32x2 %0, %1, %2;" : "=l"(acc) : "l"(p), "l"(acc));
}
__device__ __forceinline__ float2 u2f(u64 v)
{
    float2 r;
    asm("mov.b64 {%0, %1}, %2;" : "=f"(r.x), "=f"(r.y) : "l"(v));
    return r;
}
__device__ __forceinline__ uint32_t s2u(const void* p)
{
    uint32_t a;
    asm("{ .reg .u64 t; cvta.to.shared.u64 t, %1; cvt.u32.u64 %0, t; }" : "=r"(a) : "l"(p));
    return a;
}
__device__ __forceinline__ uint32_t mapa_u32(uint32_t a, uint32_t r)
{
    uint32_t d;
    asm("mapa.shared::cluster.u32 %0, %1, %2;" : "=r"(d) : "r"(a), "r"(r));
    return d;
}
__device__ __forceinline__ void st_clu(uint32_t a, unsigned v)
{
    asm volatile("st.shared::cluster.u32 [%0], %1;" :: "r"(a), "r"(v) : "memory");
}
__device__ __forceinline__ void mbar_init(uint32_t a, unsigned c)
{
    asm volatile("mbarrier.init.shared.b64 [%0], %1;" :: "r"(a), "r"(c) : "memory");
}
__device__ __forceinline__ void mbar_arrive_cluster(uint32_t a)
{
    asm volatile("mbarrier.arrive.shared::cluster.b64 _, [%0];" :: "r"(a) : "memory");
}
__device__ __forceinline__ void mbar_wait(uint32_t a, unsigned ph)
{
    unsigned done;
    asm volatile("{\n\t.reg .pred p;\n\t"
                 "mbarrier.try_wait.parity.acquire.cluster.shared::cta.b64 p, [%1], %2;\n\t"
                 "selp.b32 %0, 1, 0, p;\n\t}"
                 : "=r"(done) : "r"(a), "r"(ph) : "memory");
    while (!done) {
        asm volatile("{\n\t.reg .pred p;\n\t"
                     "mbarrier.try_wait.parity.acquire.cluster.shared::cta.b64 p, [%1], %2, 0x989680;\n\t"
                     "selp.b32 %0, 1, 0, p;\n\t}"
                     : "=r"(done) : "r"(a), "r"(ph) : "memory");
    }
}
#define CLUSTER_SYNC_() do { \
    asm volatile("barrier.cluster.arrive.aligned;" ::: "memory"); \
    asm volatile("barrier.cluster.wait.aligned;" ::: "memory"); } while (0)

// ---------------- shared memory map (float offsets) ----------------
#define SM_DRV    0        // 9408 = 2 x 4704
#define SM_SKB    9408     // 1176
#define SM_M12A   10584    // 9408
#define SM_M12C   19992    // 1600 (8 oc x 100 x2)
#define SM_PARTB  21592    // 4800 (6 ic x 8 oc x 100)
#define SM_SKE    26392    // 120
#define SM_M12F   26512    // 168
#define SM_SKF    26680    // 84
#define SM_M12G   26764    // 20
#define SM_ACC    26784    // 10
#define SM_MBAR   26796    // 4 floats = 2 u64 mbarriers (full/ack per slot)
#define SM_WCNT   26800    // 32 ints (2 slots x 16)
#define SM_LIST   26832    // 896 ints (2 slots x 14 segs x 32)
#define SM_W2     27728    // 2400
#define SM_FW1    30128    // 10080
#define SM_FW2    40208    // 840
#define SM_TOTAL  41048
#define SMEM_BYTES (SM_TOTAL * 4)
#define SM_ZBEG   SM_SKB
#define SM_ZEND   SM_W2
#define PM_XF     0
#define PM_W1     1024

__global__ void __launch_bounds__(1024, 1) __cluster_dims__(2, 1, 1)
fused_kernel(const float* __restrict__ image, const float* __restrict__ w1,
             const float* __restrict__ w2, const float* __restrict__ fw1,
             const float* __restrict__ fw2, float* __restrict__ out)
{
    extern __shared__ float sm[];
    const int tid  = threadIdx.x;
    const int lane = tid & 31;
    const int wrp  = tid >> 5;

    if (blockIdx.x >= N_SIM) {
        // ================= PRODUCER =================
        const int p = blockIdx.x - N_SIM;
        if (tid < 150) sm[PM_W1 + tid] = w1[tid];
        __syncthreads();
        const int c1_c  = tid / 112;
        const int c1_r  = tid % 112;
        const int c1_oy = c1_r >> 2;
        const int c1_x0 = (c1_r & 3) * 7;

        for (int idx = p; idx < N_TILES; idx += N_PROD) {
            int t = idx >> 5, b = idx & 31;
            unsigned k0, k1;
            threefry(0u, 1u, 0u, (unsigned)t, k0, k1);
            unsigned o0, o1;
            threefry(k0, k1, 0u, (unsigned)(b * 1024 + tid), o0, o1);
            unsigned bits = o0 ^ o1;
            float u = __uint_as_float(0x3f800000u | (bits >> 9)) - 1.0f;
            float r = __ldg(image + b * 1024 + tid) * 0.1953125f;
            sm[PM_XF + tid] = (r > u) ? 1.f : 0.f;
            __syncthreads();

            if (tid < 672) {
                const float* wr = sm + PM_W1 + c1_c * 25;
                float acc[7];
#pragma unroll
                for (int o = 0; o < 7; o++) acc[o] = 0.f;
#pragma unroll
                for (int ky = 0; ky < 5; ky++) {
                    const float* row = sm + PM_XF + (c1_oy + ky) * 32 + c1_x0;
                    float in[11];
#pragma unroll
                    for (int q = 0; q < 11; q++) in[q] = row[q];
#pragma unroll
                    for (int kx = 0; kx < 5; kx++) {
                        float wv = wr[ky * 5 + kx];
#pragma unroll
                        for (int o = 0; o < 7; o++)
                            acc[o] = fmaf(wv, in[kx + o], acc[o]);
                    }
                }
                float* outp = g_drive1 + (size_t)idx * 4704
                            + c1_c * 784 + c1_oy * 28 + c1_x0;
#pragma unroll
                for (int o = 0; o < 7; o++) outp[o] = acc[o];
            }
            __syncthreads();
            if (tid == 0) {
                __threadfence();
                ((volatile int*)g_ready)[idx] = 1;
            }
        }
        return;
    }

    // ================= SIM pair: rank0 = layers 3..7, rank1 = feeder =================
    const int rank = blockIdx.x & 1;
    const int b    = blockIdx.x >> 1;
    int* const wcnt  = (int*)(sm + SM_WCNT);
    int* const listi = (int*)(sm + SM_LIST);

    const uint32_t myBase = s2u(sm);
    const uint32_t peer0  = mapa_u32(myBase, 0);   // rank0's smem
    const uint32_t peer1  = mapa_u32(myBase, 1);   // rank1's smem
    const uint32_t mbarLocal = myBase + SM_MBAR * 4;

    for (int i = tid; i < 2400;  i += 1024) sm[SM_W2  + i] = w2[i];
    if (rank == 0) {
        for (int i = tid; i < 10080; i += 1024) sm[SM_FW1 + i] = fw1[i];
        for (int i = tid; i < 840;   i += 1024) sm[SM_FW2 + i] = fw2[i];
    }
    for (int i = tid; i < (SM_ZEND - SM_ZBEG); i += 1024) sm[SM_ZBEG + i] = 0.0f;
    if (tid == 0) {
        while (((volatile int*)g_ready)[b] == 0) __nanosleep(64);
    }
    __syncthreads();
    __threadfence();
    {
        const float4* src = (const float4*)(g_drive1 + (size_t)b * 4704);
        float4* dst = (float4*)(sm + SM_DRV);
        for (int i = tid; i < 1176; i += 1024) dst[i] = src[i];
    }
    if (tid == 0) {
        // rank0: "full" barriers (256 arrivals from rank1). rank1: "ack" (1 arrival).
        mbar_init(mbarLocal,     rank == 0 ? 256u : 1u);
        mbar_init(mbarLocal + 8, rank == 0 ? 256u : 1u);
    }
    __syncthreads();
    CLUSTER_SYNC_();

    // ---- static mappings ----
    const int a_l  = tid - 320;                // A: tids [320,908)
    const int a_c  = a_l / 98;
    const int a_r  = a_l % 98;
    const int a_by = a_r / 7;
    const int a_p  = a_r % 7;
    const int b1_oc8 = tid & 7;                // B1: tid<240
    const int b1_g   = tid >> 3;
    const int b1_ic  = b1_g / 5;
    const int b1_oy2 = b1_g % 5;
    const int c_o2 = tid >> 3;                 // C: tid<480
    const int c_j  = tid & 7;
    const int d_g  = tid >> 3;                 // D: tid<672
    const int d_j  = tid & 7;

    float pm1[2] = {0.f, 0.f}, pm2[2] = {0.f, 0.f};
    float qm1 = 0.f, qm2 = 0.f;
    float em1a = 0.f, em2a = 0.f, em1b = 0.f, em2b = 0.f;

#pragma unroll 1
    for (int t = 0; t < T_STEPS; t++) {
        const int s = t & 1;
        // ---- P1: A(t) on 320..907  ||  rank0: E(t-1) on warps 0..9 ----
        if (tid >= 320 && tid < 908) {
            const float* dp = sm + SM_DRV + s * 4704
                            + a_c * 784 + (2 * a_by) * 28 + 4 * a_p;
            float4 v0 = *(const float4*)dp;
            float4 v1 = *(const float4*)(dp + 28);
            float acc[8] = {v0.x, v0.y, v0.z, v0.w, v1.x, v1.y, v1.z, v1.w};
            int ob = a_c * 784 + (2 * a_by) * 28 + 4 * a_p;
            float ps[2] = {0.f, 0.f};
#pragma unroll
            for (int q = 0; q < 8; q++) {
                int oy = q >> 2, j = q & 3;
                int o = ob + oy * 28 + j;
                float2 m = *(float2*)(sm + SM_M12A + 2 * o);
                float oms = (m.y > 0.3f) ? 0.f : 1.f;
                float n1 = m.x * 0.25f * oms + acc[q];
                float n2 = m.y * 0.25f * oms + 0.5f * n1;
                *(float2*)(sm + SM_M12A + 2 * o) = make_float2(n1, n2);
                ps[j >> 1] += (n2 > 0.3f) ? 1.f : 0.f;
            }
#pragma unroll
            for (int h = 0; h < 2; h++) {
                float d   = 0.25f * ps[h];
                float oms = (pm2[h] > 0.3f) ? 0.f : 1.f;
                float n1  = pm1[h] * 0.25f * oms + d;
                float n2  = pm2[h] * 0.25f * oms + 0.5f * n1;
                pm1[h] = n1; pm2[h] = n2;
                sm[SM_SKB + a_c * 196 + a_by * 14 + 2 * a_p + h] = (n2 > 0.3f) ? 1.f : 0.f;
            }
        } else if (rank == 0 && wrp < 10 && t > 0) {
            const float* wp = sm + SM_FW2 + wrp * 84;
            float sv = 0.f;
            for (int k = lane; k < 84; k += 32) sv = fmaf(wp[k], sm[SM_SKF + k], sv);
#pragma unroll
            for (int d2 = 16; d2 > 0; d2 >>= 1) sv += __shfl_xor_sync(0xffffffffu, sv, d2);
            if (lane == 0) {
                float2 m = *(float2*)(sm + SM_M12G + 2 * wrp);
                float oms = (m.y > 0.3f) ? 0.f : 1.f;
                float n1 = m.x * 0.25f * oms + sv;
                float n2 = m.y * 0.25f * oms + 0.5f * n1;
                *(float2*)(sm + SM_M12G + 2 * wrp) = make_float2(n1, n2);
                sm[SM_ACC + wrp] += (n2 > 0.3f) ? 1.f : 0.f;
            }
        }
        __syncthreads();

        // ---- P2: B1 half (8 oc) || drive prefetch ----
        if (tid < 240) {
            const int oc = rank * 8 + b1_oc8;
            const float* wr = sm + SM_W2 + (oc * 6 + b1_ic) * 25;
            const float* ib = sm + SM_SKB + b1_ic * 196;
            float acc[20];
#pragma unroll
            for (int q = 0; q < 20; q++) acc[q] = 0.f;
#pragma unroll
            for (int r = 0; r < 6; r++) {
                const float2* rp = (const float2*)(ib + (2 * b1_oy2 + r) * 14);
                float in[14];
#pragma unroll
                for (int k = 0; k < 7; k++) {
                    float2 v = rp[k];
                    in[2 * k] = v.x; in[2 * k + 1] = v.y;
                }
                if (r < 5) {
#pragma unroll
                    for (int kx = 0; kx < 5; kx++) {
                        float wv = wr[r * 5 + kx];
#pragma unroll
                        for (int ox = 0; ox < 10; ox++)
                            acc[ox] = fmaf(wv, in[kx + ox], acc[ox]);
                    }
                }
                if (r >= 1) {
#pragma unroll
                    for (int kx = 0; kx < 5; kx++) {
                        float wv = wr[(r - 1) * 5 + kx];
#pragma unroll
                        for (int ox = 0; ox < 10; ox++)
                            acc[10 + ox] = fmaf(wv, in[kx + ox], acc[10 + ox]);
                    }
                }
            }
            float2* pp = (float2*)(sm + SM_PARTB + b1_ic * 800 + b1_oc8 * 100 + (2 * b1_oy2) * 10);
#pragma unroll
            for (int q = 0; q < 10; q++)
                pp[q] = make_float2(acc[2 * q], acc[2 * q + 1]);
        } else if (tid >= 256 && tid < 512 && t + 1 < T_STEPS) {
            int idx = (t + 1) * 32 + b;
            if (lane == 0) {
                while (((volatile int*)g_ready)[idx] == 0) __nanosleep(64);
            }
            __syncwarp();
            __threadfence();
            const float4* src = (const float4*)(g_drive1 + (size_t)idx * 4704);
            float4* dst = (float4*)(sm + SM_DRV + ((t + 1) & 1) * 4704);
            for (int i = tid - 256; i < 1176; i += 256) dst[i] = src[i];
        }
        __syncthreads();

        // ---- B2 compute (both ranks, tid<200) ----
        bool spiked = false;
        int myk = 0;
        unsigned bm = 0; int cnt = 0, pos = 0;
        if (tid < 224) {
            if (tid < 200) {
                int oc8 = tid / 25, rem = tid % 25, py = rem / 5, px = rem % 5;
                float s00 = 0.f, s01 = 0.f, s10 = 0.f, s11 = 0.f;
#pragma unroll
                for (int ic = 0; ic < 6; ic++) {
                    const float* pb = sm + SM_PARTB + ic * 800 + oc8 * 100;
                    float2 va = *(const float2*)(pb + (2 * py) * 10 + 2 * px);
                    float2 vb = *(const float2*)(pb + (2 * py + 1) * 10 + 2 * px);
                    s00 += va.x; s01 += va.y; s10 += vb.x; s11 += vb.y;
                }
                float dr0[4] = {s00, s01, s10, s11};
                float psum = 0.f;
                int ob = oc8 * 100 + (2 * py) * 10 + 2 * px;
#pragma unroll
                for (int q = 0; q < 4; q++) {
                    int o = ob + (q >> 1) * 10 + (q & 1);
                    float2 m = *(float2*)(sm + SM_M12C + 2 * o);
                    float oms = (m.y > 0.3f) ? 0.f : 1.f;
                    float n1 = m.x * 0.25f * oms + dr0[q];
                    float n2 = m.y * 0.25f * oms + 0.5f * n1;
                    *(float2*)(sm + SM_M12C + 2 * o) = make_float2(n1, n2);
                    psum += (n2 > 0.3f) ? 1.f : 0.f;
                }
                float d   = 0.25f * psum;
                float oms = (qm2 > 0.3f) ? 0.f : 1.f;
                float n1  = qm1 * 0.25f * oms + d;
                float n2  = qm2 * 0.25f * oms + 0.5f * n1;
                qm1 = n1; qm2 = n2;
                if (n2 > 0.3f) { spiked = true; myk = rank * 200 + tid; }
            }
            bm  = __ballot_sync(0xffffffffu, spiked);
            cnt = __popc(bm);
            pos = __popc(bm & ((1u << lane) - 1u));
        }

        if (rank == 0) {
            // ---- P3: local segments 0-6 + wait for rank1's data ----
            if (tid < 224) {
                if (spiked) listi[s * 448 + wrp * 32 + pos] = myk;
                if (lane == cnt) listi[s * 448 + wrp * 32 + lane] = 400;
                if (lane == 0) wcnt[s * 16 + wrp] = cnt;
            } else if (tid == 1023) {
                mbar_wait(mbarLocal + s * 8, (unsigned)((t >> 1) & 1));
            }
            __syncthreads();

            // ---- P4: fused conv3 gather over 14 segments + lif5 ----
            if (tid < 480) {
                const u64* w3p = (const u64*)g_w3t;
                u64 cacc = 0ull;
                for (int w = c_j; w < 14; w += 8) {
                    int n = wcnt[s * 16 + w];
                    const int* seg = listi + s * 448 + w * 32;
                    for (int j = 0; j < n; j += 2) {
                        int k0 = seg[j];
                        int k1 = seg[j + 1];
                        u64 v0 = __ldg(w3p + k0 * 60 + c_o2);
                        u64 v1 = __ldg(w3p + k1 * 60 + c_o2);
                        add2(cacc, v0);
                        add2(cacc, v1);
                    }
                }
                add2(cacc, __shfl_xor_sync(0xffffffffu, cacc, 4));
                add2(cacc, __shfl_xor_sync(0xffffffffu, cacc, 2));
                add2(cacc, __shfl_xor_sync(0xffffffffu, cacc, 1));
                if (c_j == 0) {
                    float2 v = u2f(cacc);
                    float oms = (em2a > 0.3f) ? 0.f : 1.f;
                    float n1  = em1a * 0.25f * oms + v.x;
                    float n2  = em2a * 0.25f * oms + 0.5f * n1;
                    em1a = n1; em2a = n2;
                    sm[SM_SKE + 2 * c_o2] = (n2 > 0.3f) ? 1.f : 0.f;
                    float omsb = (em2b > 0.3f) ? 0.f : 1.f;
                    float n1b  = em1b * 0.25f * omsb + v.y;
                    float n2b  = em2b * 0.25f * omsb + 0.5f * n1b;
                    em1b = n1b; em2b = n2b;
                    sm[SM_SKE + 2 * c_o2 + 1] = (n2b > 0.3f) ? 1.f : 0.f;
                }
            }
            __syncthreads();

            // ---- P5: D (fc1+lif6) + ack to rank1 ----
            if (tid < 672) {
                const float* wp = sm + SM_FW1 + d_g * 120;
                float sv = 0.f;
#pragma unroll
                for (int k = d_j; k < 120; k += 8) sv = fmaf(wp[k], sm[SM_SKE + k], sv);
                sv += __shfl_xor_sync(0xffffffffu, sv, 4);
                sv += __shfl_xor_sync(0xffffffffu, sv, 2);
                sv += __shfl_xor_sync(0xffffffffu, sv, 1);
                if (d_j == 0) {
                    float2 m = *(float2*)(sm + SM_M12F + 2 * d_g);
                    float oms = (m.y > 0.3f) ? 0.f : 1.f;
                    float n1 = m.x * 0.25f * oms + sv;
                    float n2 = m.y * 0.25f * oms + 0.5f * n1;
                    *(float2*)(sm + SM_M12F + 2 * d_g) = make_float2(n1, n2);
                    sm[SM_SKF + d_g] = (n2 > 0.3f) ? 1.f : 0.f;
                }
            } else if (tid == 1023) {
                mbar_arrive_cluster(peer1 + (SM_MBAR + s * 2) * 4);  // ack slot s
            }
            __syncthreads();
        } else {
            // ---- rank1 P3a: wait ack for slot s (t>=2) ----
            if (tid == 1023 && t >= 2) {
                mbar_wait(mbarLocal + s * 8, (unsigned)(((t >> 1) - 1) & 1));
            }
            __syncthreads();
            // ---- rank1 P3b: remote writes (segments 7-13) + arrive ----
            if (tid < 256) {
                if (spiked)
                    st_clu(peer0 + (SM_LIST + s * 448 + (7 + wrp) * 32 + pos) * 4,
                           (unsigned)myk);
                if (wrp < 7 && lane == cnt)
                    st_clu(peer0 + (SM_LIST + s * 448 + (7 + wrp) * 32 + lane) * 4, 400u);
                if (wrp < 7 && lane == 0)
                    st_clu(peer0 + (SM_WCNT + s * 16 + 7 + wrp) * 4, (unsigned)cnt);
                mbar_arrive_cluster(peer0 + (SM_MBAR + s * 2) * 4);  // full slot s
            }
            __syncthreads();
        }
    }

    if (rank == 0) {
        // drain: E(T_STEPS-1)
        if (wrp < 10) {
            const float* wp = sm + SM_FW2 + wrp * 84;
            float sv = 0.f;
            for (int k = lane; k < 84; k += 32) sv = fmaf(wp[k], sm[SM_SKF + k], sv);
#pragma unroll
            for (int d2 = 16; d2 > 0; d2 >>= 1) sv += __shfl_xor_sync(0xffffffffu, sv, d2);
            if (lane == 0) {
                float2 m = *(float2*)(sm + SM_M12G + 2 * wrp);
                float oms = (m.y > 0.3f) ? 0.f : 1.f;
                float n1 = m.x * 0.25f * oms + sv;
                float n2 = m.y * 0.25f * oms + 0.5f * n1;
                sm[SM_ACC + wrp] += (n2 > 0.3f) ? 1.f : 0.f;
            }
        }
        __syncthreads();
        if (tid < 10)
            out[b * 10 + tid] = sm[SM_ACC + tid] * (1.0f / 512.0f);
    }
    CLUSTER_SYNC_();
}

extern "C" void kernel_launch(void* const* d_in, const int* in_sizes, int n_in,
                              void* d_out, int out_size)
{
    const float* image = (const float*)d_in[0];
    const float* w1    = (const float*)d_in[1];
    const float* w2    = (const float*)d_in[2];
    const float* w3    = (const float*)d_in[3];
    const float* fw1   = (const float*)d_in[4];
    const float* fw2   = (const float*)d_in[5];
    float* out = (float*)d_out;

    reset_kernel<<<(N_TILES + 1023) / 1024, 1024>>>();
    w3t_kernel<<<(48120 + 255) / 256, 256>>>(w3);
    cudaFuncSetAttribute(fused_kernel, cudaFuncAttributeMaxDynamicSharedMemorySize, SMEM_BYTES);
    fused_kernel<<<N_SIM + N_PROD, 1024, SMEM_BYTES>>>(image, w1, w2, fw1, fw2, out);
}